// round 3
// baseline (speedup 1.0000x reference)
#include <cuda_runtime.h>
#include <math.h>

#define T_TOK   16384
#define DIM     2048
#define N_EXP   64
#define NC      128        // combined columns: 64 gate + 64 noise
#define TM      32         // tokens per block
#define BK      32         // k-tile
#define NTILES  (DIM / BK) // 64
#define TOPK    8

// scratch: combined logits [T_TOK][NC]  (8 MB, static device array — allowed)
__device__ float g_logits[(size_t)T_TOK * NC];

typedef unsigned long long ull;

__device__ __forceinline__ ull pack2(float lo, float hi) {
    ull r;
    asm("mov.b64 %0, {%1, %2};" : "=l"(r) : "f"(lo), "f"(hi));
    return r;
}
__device__ __forceinline__ void unpack2(ull v, float& lo, float& hi) {
    asm("mov.b64 {%0, %1}, %2;" : "=f"(lo), "=f"(hi) : "l"(v));
}
__device__ __forceinline__ void fma2(ull& d, ull a, ull b) {
    asm("fma.rn.f32x2 %0, %1, %2, %3;" : "=l"(d) : "l"(a), "l"(b), "l"(d));
}

// ---------------------------------------------------------------------------
// Kernel 1: C[t][0:64] = H[t]·Wg^T, C[t][64:128] = H[t]·Wn^T
// fp32 FFMA2, chunk-of-128 promotion into double accumulators.
// Numerics (per-output fma order, f32x2 pairing, chunk boundaries) are
// bitwise identical to the R2 passing kernel — only scheduling changed.
// 256 thr, 4x4 thread tile, occ 3, double-buffered smem, 1 sync/tile.
// ---------------------------------------------------------------------------
__global__ void __launch_bounds__(256, 3)
router_gemm_kernel(const float* __restrict__ H,
                   const float* __restrict__ Wg,
                   const float* __restrict__ Wn) {
    __shared__ float As[2][BK][TM];   // 2 * 4 KB
    __shared__ float Bs[2][BK][NC];   // 2 * 16 KB

    const int tid = threadIdx.x;
    const int tx  = tid & 31;      // col groups: pairs {2tx+64i, +1}, i<2
    const int ty  = tid >> 5;      // row group: rows 4ty..4ty+3 (0..7)
    const int m0  = blockIdx.x * TM;

    // loaders
    const int ra = tid & 31,  ja = tid >> 5;          // A: 1 float4 (k slot ja)
    const int rb = tid & 127, jb = (tid >> 7) * 4;    // B: 4 float4 (slots jb..jb+3)

    const float4* hrow = (const float4*)(H + (size_t)(m0 + ra) * DIM);
    const float*  wp   = (rb < N_EXP) ? (Wg + (size_t)rb * DIM)
                                      : (Wn + (size_t)(rb - N_EXP) * DIM);
    const float4* wrow = (const float4*)wp;

    ull    acc[4][2];     // fp32x2 chunk accumulators [row j][col-pair i]
    double dacc[4][4];    // exact chunk sums           [row j][col]
#pragma unroll
    for (int j = 0; j < 4; j++) {
#pragma unroll
        for (int i = 0; i < 2; i++) acc[j][i] = 0ULL;
#pragma unroll
        for (int c = 0; c < 4; c++) dacc[j][c] = 0.0;
    }

    // prefetch tile 0 into registers
    float4 av, bv[4];
    av = hrow[ja];
#pragma unroll
    for (int f = 0; f < 4; f++) bv[f] = wrow[jb + f];

    // store tile 0 into buffer 0
    {
        const int ka = ja * 4;
        As[0][ka+0][ra] = av.x; As[0][ka+1][ra] = av.y;
        As[0][ka+2][ra] = av.z; As[0][ka+3][ra] = av.w;
#pragma unroll
        for (int f = 0; f < 4; f++) {
            const int kb = (jb + f) * 4;
            Bs[0][kb+0][rb] = bv[f].x; Bs[0][kb+1][rb] = bv[f].y;
            Bs[0][kb+2][rb] = bv[f].z; Bs[0][kb+3][rb] = bv[f].w;
        }
    }
    __syncthreads();

    int buf = 0;
    for (int tile = 0; tile < NTILES; tile++) {
        // prefetch next tile (global) while FMAs run
        const bool more = (tile + 1 < NTILES);
        if (more) {
            const int base = (tile + 1) * (BK / 4);
            av = hrow[base + ja];
#pragma unroll
            for (int f = 0; f < 4; f++) bv[f] = wrow[base + jb + f];
        }

        // compute on current buffer
#pragma unroll
        for (int k = 0; k < BK; k++) {
            float4 a4 = *(const float4*)&As[buf][k][ty * 4];  // LDS.128 (bcast)
            ull a2[4] = { pack2(a4.x, a4.x), pack2(a4.y, a4.y),
                          pack2(a4.z, a4.z), pack2(a4.w, a4.w) };
            ull b2[2];
#pragma unroll
            for (int i = 0; i < 2; i++)
                b2[i] = *(const ull*)&Bs[buf][k][2 * tx + 64 * i];  // LDS.64
#pragma unroll
            for (int j = 0; j < 4; j++)
#pragma unroll
                for (int i = 0; i < 2; i++)
                    fma2(acc[j][i], a2[j], b2[i]);
        }

        // store prefetched tile into the other buffer
        if (more) {
            const int nb = buf ^ 1;
            const int ka = ja * 4;
            As[nb][ka+0][ra] = av.x; As[nb][ka+1][ra] = av.y;
            As[nb][ka+2][ra] = av.z; As[nb][ka+3][ra] = av.w;
#pragma unroll
            for (int f = 0; f < 4; f++) {
                const int kb = (jb + f) * 4;
                Bs[nb][kb+0][rb] = bv[f].x; Bs[nb][kb+1][rb] = bv[f].y;
                Bs[nb][kb+2][rb] = bv[f].z; Bs[nb][kb+3][rb] = bv[f].w;
            }
        }
        __syncthreads();
        buf ^= 1;

        // promote chunk (128 k-values) into double accumulators
        if ((tile & 3) == 3) {
#pragma unroll
            for (int j = 0; j < 4; j++)
#pragma unroll
                for (int i = 0; i < 2; i++) {
                    float lo, hi;
                    unpack2(acc[j][i], lo, hi);
                    dacc[j][2*i]   += (double)lo;
                    dacc[j][2*i+1] += (double)hi;
                    acc[j][i] = 0ULL;
                }
        }
    }

    // write logits tile
#pragma unroll
    for (int j = 0; j < 4; j++) {
        const int m = m0 + ty * 4 + j;
        float* dst = g_logits + (size_t)m * NC;
#pragma unroll
        for (int i = 0; i < 2; i++) {
            const int c = 2 * tx + 64 * i;
            dst[c]     = (float)dacc[j][2*i];
            dst[c + 1] = (float)dacc[j][2*i+1];
        }
    }
}

// ---------------------------------------------------------------------------
// Kernel 2: one warp per token — noisy logits, softmax(64), top-8 desc
// out layout (all fp32): [vals T*8][inds T*8 (cast)][gates T*64]
// ---------------------------------------------------------------------------
__device__ __forceinline__ float softplus_f(float x) {
    return fmaxf(x, 0.0f) + log1pf(expf(-fabsf(x)));
}

__global__ void __launch_bounds__(256)
router_topk_kernel(const float* __restrict__ noise, float* __restrict__ out) {
    const int warp = (blockIdx.x * blockDim.x + threadIdx.x) >> 5;
    const int lane = threadIdx.x & 31;
    if (warp >= T_TOK) return;

    const float* row = g_logits + (size_t)warp * NC;
    const float* nz  = noise + (size_t)warp * N_EXP;

    // expert e = lane and e = lane+32
    float g0 = row[lane]      + nz[lane]      * softplus_f(row[64 + lane]);
    float g1 = row[lane + 32] + nz[lane + 32] * softplus_f(row[96 + lane]);

    // softmax over 64
    float mx = fmaxf(g0, g1);
#pragma unroll
    for (int o = 16; o > 0; o >>= 1) mx = fmaxf(mx, __shfl_xor_sync(0xffffffffu, mx, o));
    float e0 = expf(g0 - mx), e1 = expf(g1 - mx);
    float s = e0 + e1;
#pragma unroll
    for (int o = 16; o > 0; o >>= 1) s += __shfl_xor_sync(0xffffffffu, s, o);
    const float inv = 1.0f / s;
    float p0 = e0 * inv, p1 = e1 * inv;

    // write gates
    float* gates = out + (size_t)2 * T_TOK * TOPK + (size_t)warp * N_EXP;
    gates[lane]      = p0;
    gates[lane + 32] = p1;

    // top-8, sorted desc, lower index on ties (matches jax.lax.top_k)
    float v0 = p0, v1 = p1;
    float* vals = out + (size_t)warp * TOPK;
    float* inds = out + (size_t)T_TOK * TOPK + (size_t)warp * TOPK;

#pragma unroll
    for (int r = 0; r < TOPK; r++) {
        float cv; int ci;
        if (v0 >= v1) { cv = v0; ci = lane; }       // lower index wins ties
        else          { cv = v1; ci = lane + 32; }
#pragma unroll
        for (int o = 16; o > 0; o >>= 1) {
            float ov = __shfl_xor_sync(0xffffffffu, cv, o);
            int   oi = __shfl_xor_sync(0xffffffffu, ci, o);
            if (ov > cv || (ov == cv && oi < ci)) { cv = ov; ci = oi; }
        }
        if (lane == 0) {
            vals[r] = cv;
            inds[r] = (float)ci;
        }
        // remove selected
        if (ci == lane)      v0 = -INFINITY;
        if (ci == lane + 32) v1 = -INFINITY;
    }
}

// ---------------------------------------------------------------------------
extern "C" void kernel_launch(void* const* d_in, const int* in_sizes, int n_in,
                              void* d_out, int out_size) {
    const float* H     = (const float*)d_in[0];  // [4,4096,2048]
    const float* Wg    = (const float*)d_in[1];  // [64,2048]
    const float* Wn    = (const float*)d_in[2];  // [64,2048]
    const float* noise = (const float*)d_in[3];  // [4,4096,64]
    float* out = (float*)d_out;

    router_gemm_kernel<<<T_TOK / TM, 256>>>(H, Wg, Wn);
    router_topk_kernel<<<(T_TOK * 32) / 256, 256>>>(noise, out);
}

// round 4
// speedup vs baseline: 1.4752x; 1.4752x over previous
#include <cuda_runtime.h>
#include <math.h>

#define T_TOK   16384
#define DIM     2048
#define N_EXP   64
#define NC      128        // combined columns: 64 gate + 64 noise
#define TM      32         // tokens per block
#define BK      32         // k-tile
#define NTILES  (DIM / BK) // 64
#define TOPK    8

// scratch: combined logits [T_TOK][NC]  (8 MB, static device array — allowed)
__device__ float g_logits[(size_t)T_TOK * NC];

typedef unsigned long long ull;

__device__ __forceinline__ ull pack2(float lo, float hi) {
    ull r;
    asm("mov.b64 %0, {%1, %2};" : "=l"(r) : "f"(lo), "f"(hi));
    return r;
}
__device__ __forceinline__ void unpack2(ull v, float& lo, float& hi) {
    asm("mov.b64 {%0, %1}, %2;" : "=f"(lo), "=f"(hi) : "l"(v));
}
__device__ __forceinline__ void fma2(ull& d, ull a, ull b) {
    asm("fma.rn.f32x2 %0, %1, %2, %3;" : "=l"(d) : "l"(a), "l"(b), "l"(d));
}

// ---------------------------------------------------------------------------
// Kernel 1: C[t][0:64] = H[t]·Wg^T, C[t][64:128] = H[t]·Wn^T
// fp32 FFMA2, chunk-of-128 promotion into double accumulators.
// Numerics (per-output fma order, f32x2 pairing, chunk boundaries) bitwise
// identical to the R2/R3 passing kernels — only scheduling differs.
// KEY CHANGE vs R3: register cap lifted (128 vs 85) -> no local-memory
// spills of dacc/prefetch registers; occupancy 2 CTAs/SM by registers.
// ---------------------------------------------------------------------------
__global__ void __launch_bounds__(256, 2)
router_gemm_kernel(const float* __restrict__ H,
                   const float* __restrict__ Wg,
                   const float* __restrict__ Wn) {
    __shared__ float As[2][BK][TM];   // 2 * 4 KB
    __shared__ float Bs[2][BK][NC];   // 2 * 16 KB

    const int tid = threadIdx.x;
    const int tx  = tid & 31;      // col groups: pairs {2tx+64i, +1}, i<2
    const int ty  = tid >> 5;      // row group: rows 4ty..4ty+3 (0..7)
    const int m0  = blockIdx.x * TM;

    // loaders
    const int ra = tid & 31,  ja = tid >> 5;          // A: 1 float4 (k slot ja)
    const int rb = tid & 127, jb = (tid >> 7) * 4;    // B: 4 float4 (slots jb..jb+3)

    const float4* hrow = (const float4*)(H + (size_t)(m0 + ra) * DIM);
    const float*  wp   = (rb < N_EXP) ? (Wg + (size_t)rb * DIM)
                                      : (Wn + (size_t)(rb - N_EXP) * DIM);
    const float4* wrow = (const float4*)wp;

    ull    acc[4][2];     // fp32x2 chunk accumulators [row j][col-pair i]
    double dacc[4][4];    // exact chunk sums           [row j][col]
#pragma unroll
    for (int j = 0; j < 4; j++) {
#pragma unroll
        for (int i = 0; i < 2; i++) acc[j][i] = 0ULL;
#pragma unroll
        for (int c = 0; c < 4; c++) dacc[j][c] = 0.0;
    }

    // prefetch tile 0 into registers
    float4 av, bv[4];
    av = hrow[ja];
#pragma unroll
    for (int f = 0; f < 4; f++) bv[f] = wrow[jb + f];

    // store tile 0 into buffer 0
    {
        const int ka = ja * 4;
        As[0][ka+0][ra] = av.x; As[0][ka+1][ra] = av.y;
        As[0][ka+2][ra] = av.z; As[0][ka+3][ra] = av.w;
#pragma unroll
        for (int f = 0; f < 4; f++) {
            const int kb = (jb + f) * 4;
            Bs[0][kb+0][rb] = bv[f].x; Bs[0][kb+1][rb] = bv[f].y;
            Bs[0][kb+2][rb] = bv[f].z; Bs[0][kb+3][rb] = bv[f].w;
        }
    }
    __syncthreads();

    int buf = 0;
    for (int tile = 0; tile < NTILES; tile++) {
        // prefetch next tile (global) while FMAs run
        const bool more = (tile + 1 < NTILES);
        if (more) {
            const int base = (tile + 1) * (BK / 4);
            av = hrow[base + ja];
#pragma unroll
            for (int f = 0; f < 4; f++) bv[f] = wrow[base + jb + f];
        }

        // compute on current buffer
#pragma unroll
        for (int k = 0; k < BK; k++) {
            float4 a4 = *(const float4*)&As[buf][k][ty * 4];  // LDS.128 (bcast)
            ull a2[4] = { pack2(a4.x, a4.x), pack2(a4.y, a4.y),
                          pack2(a4.z, a4.z), pack2(a4.w, a4.w) };
            ull b2[2];
#pragma unroll
            for (int i = 0; i < 2; i++)
                b2[i] = *(const ull*)&Bs[buf][k][2 * tx + 64 * i];  // LDS.64
#pragma unroll
            for (int j = 0; j < 4; j++)
#pragma unroll
                for (int i = 0; i < 2; i++)
                    fma2(acc[j][i], a2[j], b2[i]);
        }

        // store prefetched tile into the other buffer
        if (more) {
            const int nb = buf ^ 1;
            const int ka = ja * 4;
            As[nb][ka+0][ra] = av.x; As[nb][ka+1][ra] = av.y;
            As[nb][ka+2][ra] = av.z; As[nb][ka+3][ra] = av.w;
#pragma unroll
            for (int f = 0; f < 4; f++) {
                const int kb = (jb + f) * 4;
                Bs[nb][kb+0][rb] = bv[f].x; Bs[nb][kb+1][rb] = bv[f].y;
                Bs[nb][kb+2][rb] = bv[f].z; Bs[nb][kb+3][rb] = bv[f].w;
            }
        }
        __syncthreads();
        buf ^= 1;

        // promote chunk (128 k-values) into double accumulators
        if ((tile & 3) == 3) {
#pragma unroll
            for (int j = 0; j < 4; j++)
#pragma unroll
                for (int i = 0; i < 2; i++) {
                    float lo, hi;
                    unpack2(acc[j][i], lo, hi);
                    dacc[j][2*i]   += (double)lo;
                    dacc[j][2*i+1] += (double)hi;
                    acc[j][i] = 0ULL;
                }
        }
    }

    // write logits tile
#pragma unroll
    for (int j = 0; j < 4; j++) {
        const int m = m0 + ty * 4 + j;
        float* dst = g_logits + (size_t)m * NC;
#pragma unroll
        for (int i = 0; i < 2; i++) {
            const int c = 2 * tx + 64 * i;
            dst[c]     = (float)dacc[j][2*i];
            dst[c + 1] = (float)dacc[j][2*i+1];
        }
    }
}

// ---------------------------------------------------------------------------
// Kernel 2: one warp per token — noisy logits, softmax(64), top-8 desc
// out layout (all fp32): [vals T*8][inds T*8 (cast)][gates T*64]
// ---------------------------------------------------------------------------
__device__ __forceinline__ float softplus_f(float x) {
    return fmaxf(x, 0.0f) + log1pf(expf(-fabsf(x)));
}

__global__ void __launch_bounds__(256)
router_topk_kernel(const float* __restrict__ noise, float* __restrict__ out) {
    const int warp = (blockIdx.x * blockDim.x + threadIdx.x) >> 5;
    const int lane = threadIdx.x & 31;
    if (warp >= T_TOK) return;

    const float* row = g_logits + (size_t)warp * NC;
    const float* nz  = noise + (size_t)warp * N_EXP;

    // expert e = lane and e = lane+32
    float g0 = row[lane]      + nz[lane]      * softplus_f(row[64 + lane]);
    float g1 = row[lane + 32] + nz[lane + 32] * softplus_f(row[96 + lane]);

    // softmax over 64
    float mx = fmaxf(g0, g1);
#pragma unroll
    for (int o = 16; o > 0; o >>= 1) mx = fmaxf(mx, __shfl_xor_sync(0xffffffffu, mx, o));
    float e0 = expf(g0 - mx), e1 = expf(g1 - mx);
    float s = e0 + e1;
#pragma unroll
    for (int o = 16; o > 0; o >>= 1) s += __shfl_xor_sync(0xffffffffu, s, o);
    const float inv = 1.0f / s;
    float p0 = e0 * inv, p1 = e1 * inv;

    // write gates
    float* gates = out + (size_t)2 * T_TOK * TOPK + (size_t)warp * N_EXP;
    gates[lane]      = p0;
    gates[lane + 32] = p1;

    // top-8, sorted desc, lower index on ties (matches jax.lax.top_k)
    float v0 = p0, v1 = p1;
    float* vals = out + (size_t)warp * TOPK;
    float* inds = out + (size_t)T_TOK * TOPK + (size_t)warp * TOPK;

#pragma unroll
    for (int r = 0; r < TOPK; r++) {
        float cv; int ci;
        if (v0 >= v1) { cv = v0; ci = lane; }       // lower index wins ties
        else          { cv = v1; ci = lane + 32; }
#pragma unroll
        for (int o = 16; o > 0; o >>= 1) {
            float ov = __shfl_xor_sync(0xffffffffu, cv, o);
            int   oi = __shfl_xor_sync(0xffffffffu, ci, o);
            if (ov > cv || (ov == cv && oi < ci)) { cv = ov; ci = oi; }
        }
        if (lane == 0) {
            vals[r] = cv;
            inds[r] = (float)ci;
        }
        // remove selected
        if (ci == lane)      v0 = -INFINITY;
        if (ci == lane + 32) v1 = -INFINITY;
    }
}

// ---------------------------------------------------------------------------
extern "C" void kernel_launch(void* const* d_in, const int* in_sizes, int n_in,
                              void* d_out, int out_size) {
    const float* H     = (const float*)d_in[0];  // [4,4096,2048]
    const float* Wg    = (const float*)d_in[1];  // [64,2048]
    const float* Wn    = (const float*)d_in[2];  // [64,2048]
    const float* noise = (const float*)d_in[3];  // [4,4096,64]
    float* out = (float*)d_out;

    router_gemm_kernel<<<T_TOK / TM, 256>>>(H, Wg, Wn);
    router_topk_kernel<<<(T_TOK * 32) / 256, 256>>>(noise, out);
}